// round 1
// baseline (speedup 1.0000x reference)
#include <cuda_runtime.h>

// EHD layer, fully fused:
//   x[16,1,1024,1024] --3x3 valid conv with 8 filters--> y[16,8,1022,1022]
//   argmax over 8 filters, threshold 0.9 -> index in [0,8] (8 = "no edge")
//   one-hot over 9 bins -> 5x5 box mean -> out[16,9,1018,1018]
//
// Trick: 9 bins x 5 bits packed into one uint64 (max window count 25 < 32),
// so the per-bin windowed count is two separable 5-tap integer sums on
// packed words held in shared memory.

#define IN_H   1024
#define IN_W   1024
#define NOR    8
#define NBINS  9          // NOR + 1
#define IDX_H  1022       // conv-valid grid
#define IDX_W  1022
#define OUT_H  1018       // after 5x5 valid pool
#define OUT_W  1018
#define THRESH 0.9f

#define TX 32             // output tile
#define TY 32
#define ITX (TX + 4)      // 36: index tile (window halo)
#define ITY (TY + 4)
#define LTX (TX + 6)      // 38: input tile (conv halo on top of window halo)
#define LTY (TY + 6)

#define NTHREADS 256

__global__ __launch_bounds__(NTHREADS)
void ehd_fused_kernel(const float* __restrict__ x,
                      const float* __restrict__ masks,
                      float* __restrict__ out,
                      int batch)
{
    __shared__ float s_in[LTY][LTX + 2];                 // 38 x 40 (pad: bank-friendly)
    __shared__ float s_m[NOR * 9];                       // 72 filter taps
    __shared__ unsigned long long s_oh[ITY][ITX + 1];    // 36 x 37 packed one-hot
    __shared__ unsigned long long s_h [ITY][TX + 1];     // 36 x 33 horizontal 5-sums

    const int tid = threadIdx.x;
    const int ox  = blockIdx.x * TX;
    const int oy  = blockIdx.y * TY;
    const int b   = blockIdx.z;

    if (tid < NOR * 9) s_m[tid] = masks[tid];

    // ---- stage 1: load input tile (zero-pad out-of-range; padded values only
    // feed index pixels that no valid output window references) ----
    const float* xb = x + (size_t)b * IN_H * IN_W;
    for (int i = tid; i < LTY * LTX; i += NTHREADS) {
        int r = i / LTX, c = i % LTX;
        int gy = oy + r, gx = ox + c;
        float v = 0.0f;
        if (gy < IN_H && gx < IN_W) v = xb[(size_t)gy * IN_W + gx];
        s_in[r][c] = v;
    }
    __syncthreads();

    // filter taps -> registers (hoisted out of the pixel loop; avoids 72
    // broadcast LDS per pixel)
    float m[NOR * 9];
#pragma unroll
    for (int k = 0; k < NOR * 9; k++) m[k] = s_m[k];

    // ---- stage 2: conv + argmax + threshold + pack one-hot ----
    for (int i = tid; i < ITY * ITX; i += NTHREADS) {
        int r = i / ITX, c = i % ITX;

        float w0 = s_in[r    ][c    ], w1 = s_in[r    ][c + 1], w2 = s_in[r    ][c + 2];
        float w3 = s_in[r + 1][c    ], w4 = s_in[r + 1][c + 1], w5 = s_in[r + 1][c + 2];
        float w6 = s_in[r + 2][c    ], w7 = s_in[r + 2][c + 1], w8 = s_in[r + 2][c + 2];

        float best = -3.4e38f;
        int   bi   = 0;
#pragma unroll
        for (int f = 0; f < NOR; f++) {
            const float* mf = m + f * 9;
            float acc = w0 * mf[0];
            acc = fmaf(w1, mf[1], acc);
            acc = fmaf(w2, mf[2], acc);
            acc = fmaf(w3, mf[3], acc);
            acc = fmaf(w4, mf[4], acc);
            acc = fmaf(w5, mf[5], acc);
            acc = fmaf(w6, mf[6], acc);
            acc = fmaf(w7, mf[7], acc);
            acc = fmaf(w8, mf[8], acc);
            // strict > keeps the FIRST max (jnp.argmax tie-break)
            if (acc > best) { best = acc; bi = f; }
        }
        if (best < THRESH) bi = NOR;  // "no edge" bin

        s_oh[r][c] = 1ULL << (5 * bi);
    }
    __syncthreads();

    // ---- stage 3: horizontal 5-tap sum on packed words ----
    for (int i = tid; i < ITY * TX; i += NTHREADS) {
        int r = i / TX, c = i % TX;
        s_h[r][c] = s_oh[r][c] + s_oh[r][c + 1] + s_oh[r][c + 2]
                  + s_oh[r][c + 3] + s_oh[r][c + 4];
    }
    __syncthreads();

    // ---- stage 4: vertical 5-tap sum, unpack 9 bins, write ----
    for (int i = tid; i < TY * TX; i += NTHREADS) {
        int r = i / TX, c = i % TX;
        int gy = oy + r, gx = ox + c;
        if (gy < OUT_H && gx < OUT_W) {
            unsigned long long s = s_h[r][c] + s_h[r + 1][c] + s_h[r + 2][c]
                                 + s_h[r + 3][c] + s_h[r + 4][c];
            size_t base = ((size_t)b * NBINS) * OUT_H * OUT_W
                        + (size_t)gy * OUT_W + gx;
#pragma unroll
            for (int bin = 0; bin < NBINS; bin++) {
                float cnt = (float)((unsigned)(s >> (5 * bin)) & 31u);
                out[base + (size_t)bin * OUT_H * OUT_W] = cnt * (1.0f / 25.0f);
            }
        }
    }
}

extern "C" void kernel_launch(void* const* d_in, const int* in_sizes, int n_in,
                              void* d_out, int out_size)
{
    const float* x     = (const float*)d_in[0];   // [B,1,1024,1024]
    const float* masks = (const float*)d_in[1];   // [8,1,3,3]
    float* out = (float*)d_out;                    // [B,9,1018,1018]

    int batch = in_sizes[0] / (IN_H * IN_W);

    dim3 grid((OUT_W + TX - 1) / TX, (OUT_H + TY - 1) / TY, batch);
    ehd_fused_kernel<<<grid, NTHREADS>>>(x, masks, out, batch);
}

// round 2
// speedup vs baseline: 1.4094x; 1.4094x over previous
#include <cuda_runtime.h>

// EHD layer, fully fused, v2 (occupancy-focused):
//   x[16,1,1024,1024] --3x3 valid conv, 8 filters--> argmax+threshold ->
//   one-hot over 9 bins -> 5x5 box mean -> out[16,9,1018,1018]
//
// v2 changes vs v1:
//  - masks NOT register-resident (v1: 72 regs -> 104 regs/thr -> 2 CTAs/SM).
//    Filters-outer loop keeps only 9 mask regs live (broadcast LDS per filter).
//  - each thread computes 4 vertically-adjacent index pixels from one 6x3
//    window strip held in 18 regs (row reuse halves input LDS).
//  - tile T=28 -> index tile 32x32: all index math is shift/mask (no /36).
//  - __launch_bounds__(256,4) pins regs at 64 -> 4 CTAs/SM, 32 warps.

#define NOR    8
#define NBINS  9
#define OUT_H  1018
#define OUT_W  1018
#define THRESH 0.9f

#define T   28            // output tile
#define IT  32            // index tile  (T+4), power of 2
#define LT  34            // input tile  (T+6)

#define NTHREADS 256

__global__ __launch_bounds__(NTHREADS, 4)
void ehd_fused_kernel(const float* __restrict__ x,
                      const float* __restrict__ masks,
                      float* __restrict__ out)
{
    __shared__ float s_in[LT][36];                    // 34x36 f32
    __shared__ float s_m[NOR * 9];                    // 72 filter taps
    __shared__ unsigned long long s_oh[IT][36];       // 32x36 packed one-hot (cols 32..35 = 0 pad)
    __shared__ unsigned long long s_h [IT][33];       // 32x33 horizontal 5-sums

    const int tid  = threadIdx.x;
    const int lane = tid & 31;
    const int wid  = tid >> 5;
    const int ox   = blockIdx.x * T;
    const int oy   = blockIdx.y * T;
    const int b    = blockIdx.z;

    if (tid < NOR * 9) s_m[tid] = masks[tid];

    // zero the halo pad columns of s_oh (cols 32..35)
    if (tid < IT * 4) s_oh[tid >> 2][32 + (tid & 3)] = 0ULL;

    // ---- stage 1: load 34x34 input tile (zero-pad OOB; pad only feeds
    // index pixels that no valid output window references) ----
    const float* xb = x + (size_t)b * (1024 * 1024);
    for (int r = wid; r < LT; r += 8) {
        const int gy = oy + r;
        for (int c = lane; c < LT; c += 32) {
            const int gx = ox + c;
            float v = 0.0f;
            if (gy < 1024 && gx < 1024) v = xb[gy * 1024 + gx];
            s_in[r][c] = v;
        }
    }
    __syncthreads();

    // ---- stage 2: conv + argmax + threshold + pack one-hot ----
    // thread -> column c = lane, rows rbase..rbase+3 (4 pixels, shared 6x3 strip)
    {
        const int c     = lane;
        const int rbase = wid << 2;

        float w[6][3];
#pragma unroll
        for (int j = 0; j < 6; j++)
#pragma unroll
            for (int k = 0; k < 3; k++)
                w[j][k] = s_in[rbase + j][c + k];

        float best[4];
        int   bi[4];
#pragma unroll
        for (int p = 0; p < 4; p++) { best[p] = -3.4e38f; bi[p] = 0; }

#pragma unroll
        for (int f = 0; f < NOR; f++) {
            const float m0 = s_m[f * 9 + 0], m1 = s_m[f * 9 + 1], m2 = s_m[f * 9 + 2];
            const float m3 = s_m[f * 9 + 3], m4 = s_m[f * 9 + 4], m5 = s_m[f * 9 + 5];
            const float m6 = s_m[f * 9 + 6], m7 = s_m[f * 9 + 7], m8 = s_m[f * 9 + 8];
#pragma unroll
            for (int p = 0; p < 4; p++) {
                float acc = w[p][0] * m0;
                acc = fmaf(w[p    ][1], m1, acc);
                acc = fmaf(w[p    ][2], m2, acc);
                acc = fmaf(w[p + 1][0], m3, acc);
                acc = fmaf(w[p + 1][1], m4, acc);
                acc = fmaf(w[p + 1][2], m5, acc);
                acc = fmaf(w[p + 2][0], m6, acc);
                acc = fmaf(w[p + 2][1], m7, acc);
                acc = fmaf(w[p + 2][2], m8, acc);
                // strict > keeps FIRST max (jnp.argmax tie-break)
                if (acc > best[p]) { best[p] = acc; bi[p] = f; }
            }
        }
#pragma unroll
        for (int p = 0; p < 4; p++) {
            const int idx = (best[p] < THRESH) ? NOR : bi[p];
            s_oh[rbase + p][c] = 1ULL << (5 * idx);
        }
    }
    __syncthreads();

    // ---- stage 3: horizontal 5-tap sum on packed words (32x32, cols 28..31 junk) ----
#pragma unroll
    for (int it = 0; it < 4; it++) {
        const int i = tid + it * NTHREADS;
        const int r = i >> 5, c = i & 31;
        s_h[r][c] = s_oh[r][c] + s_oh[r][c + 1] + s_oh[r][c + 2]
                  + s_oh[r][c + 3] + s_oh[r][c + 4];
    }
    __syncthreads();

    // ---- stage 4: vertical 5-tap sum, unpack 9 bins, store ----
    const size_t plane = (size_t)OUT_H * OUT_W;
    float* ob = out + (size_t)b * NBINS * plane;
#pragma unroll
    for (int it = 0; it < 4; it++) {
        const int i = tid + it * NTHREADS;
        const int r = i >> 5, c = i & 31;
        const int gy = oy + r, gx = ox + c;
        if (r < T && c < T && gy < OUT_H && gx < OUT_W) {
            const unsigned long long s = s_h[r][c]     + s_h[r + 1][c]
                                       + s_h[r + 2][c] + s_h[r + 3][c]
                                       + s_h[r + 4][c];
            const size_t base = (size_t)gy * OUT_W + gx;
#pragma unroll
            for (int bin = 0; bin < NBINS; bin++) {
                const float cnt = (float)((unsigned)(s >> (5 * bin)) & 31u);
                ob[(size_t)bin * plane + base] = cnt * (1.0f / 25.0f);
            }
        }
    }
}

extern "C" void kernel_launch(void* const* d_in, const int* in_sizes, int n_in,
                              void* d_out, int out_size)
{
    const float* x     = (const float*)d_in[0];   // [B,1,1024,1024]
    const float* masks = (const float*)d_in[1];   // [8,1,3,3]
    float* out = (float*)d_out;                   // [B,9,1018,1018]

    const int batch = in_sizes[0] / (1024 * 1024);

    dim3 grid((OUT_W + T - 1) / T, (OUT_H + T - 1) / T, batch);
    ehd_fused_kernel<<<grid, NTHREADS>>>(x, masks, out);
}

// round 3
// speedup vs baseline: 1.4284x; 1.0135x over previous
#include <cuda_runtime.h>

// EHD layer, fully fused, v3:
//  - v2 + launch_bounds(256,5): 48 regs -> 5 CTAs/SM (40 warps, 62.5% occ)
//  - stage 4 emits float2 (column pairs): halves STG count + address math
//
// Pipeline: 3x3 conv (8 filters) -> argmax+thresh -> one-hot packed as
// uint64 (9 bins x 5 bits) -> separable 5x5 integer box sum -> *1/25.

#define NOR    8
#define NBINS  9
#define OUT_H  1018
#define OUT_W  1018
#define THRESH 0.9f

#define T   28            // output tile
#define IT  32            // index tile  (T+4), power of 2
#define LT  34            // input tile  (T+6)

#define NTHREADS 256

__global__ __launch_bounds__(NTHREADS, 5)
void ehd_fused_kernel(const float* __restrict__ x,
                      const float* __restrict__ masks,
                      float* __restrict__ out)
{
    __shared__ float s_in[LT][36];                    // 34x36 f32
    __shared__ float s_m[NOR * 9];                    // 72 filter taps
    __shared__ unsigned long long s_oh[IT][36];       // 32x36 packed one-hot (cols 32..35 = 0)
    __shared__ unsigned long long s_h [IT][33];       // 32x33 horizontal 5-sums

    const int tid  = threadIdx.x;
    const int lane = tid & 31;
    const int wid  = tid >> 5;
    const int ox   = blockIdx.x * T;
    const int oy   = blockIdx.y * T;
    const int b    = blockIdx.z;

    if (tid < NOR * 9) s_m[tid] = masks[tid];
    if (tid < IT * 4) s_oh[tid >> 2][32 + (tid & 3)] = 0ULL;  // zero halo pad cols

    // ---- stage 1: load 34x34 input tile (zero-pad OOB; the pad only feeds
    // index pixels no valid output window references) ----
    const float* xb = x + (size_t)b * (1024 * 1024);
    for (int r = wid; r < LT; r += 8) {
        const int gy = oy + r;
        for (int c = lane; c < LT; c += 32) {
            const int gx = ox + c;
            float v = 0.0f;
            if (gy < 1024 && gx < 1024) v = xb[gy * 1024 + gx];
            s_in[r][c] = v;
        }
    }
    __syncthreads();

    // ---- stage 2: conv + argmax + threshold + pack one-hot ----
    // thread -> column c = lane, rows rbase..rbase+3 (shared 6x3 window strip)
    {
        const int c     = lane;
        const int rbase = wid << 2;

        float w[6][3];
#pragma unroll
        for (int j = 0; j < 6; j++)
#pragma unroll
            for (int k = 0; k < 3; k++)
                w[j][k] = s_in[rbase + j][c + k];

        float best[4];
        int   bi[4];
#pragma unroll
        for (int p = 0; p < 4; p++) { best[p] = -3.4e38f; bi[p] = 0; }

#pragma unroll
        for (int f = 0; f < NOR; f++) {
            const float m0 = s_m[f * 9 + 0], m1 = s_m[f * 9 + 1], m2 = s_m[f * 9 + 2];
            const float m3 = s_m[f * 9 + 3], m4 = s_m[f * 9 + 4], m5 = s_m[f * 9 + 5];
            const float m6 = s_m[f * 9 + 6], m7 = s_m[f * 9 + 7], m8 = s_m[f * 9 + 8];
#pragma unroll
            for (int p = 0; p < 4; p++) {
                float acc = w[p][0] * m0;
                acc = fmaf(w[p    ][1], m1, acc);
                acc = fmaf(w[p    ][2], m2, acc);
                acc = fmaf(w[p + 1][0], m3, acc);
                acc = fmaf(w[p + 1][1], m4, acc);
                acc = fmaf(w[p + 1][2], m5, acc);
                acc = fmaf(w[p + 2][0], m6, acc);
                acc = fmaf(w[p + 2][1], m7, acc);
                acc = fmaf(w[p + 2][2], m8, acc);
                // strict > keeps FIRST max (jnp.argmax tie-break)
                if (acc > best[p]) { best[p] = acc; bi[p] = f; }
            }
        }
#pragma unroll
        for (int p = 0; p < 4; p++) {
            const int idx = (best[p] < THRESH) ? NOR : bi[p];
            s_oh[rbase + p][c] = 1ULL << (5 * idx);
        }
    }
    __syncthreads();

    // ---- stage 3: horizontal 5-tap sum on packed words (32 rows x 32 cols) ----
#pragma unroll
    for (int it = 0; it < 4; it++) {
        const int i = tid + it * NTHREADS;
        const int r = i >> 5, c = i & 31;
        s_h[r][c] = s_oh[r][c] + s_oh[r][c + 1] + s_oh[r][c + 2]
                  + s_oh[r][c + 3] + s_oh[r][c + 4];
    }
    __syncthreads();

    // ---- stage 4: vertical 5-tap sum on COLUMN PAIRS, float2 stores ----
    // units: 14 column-pairs x 28 rows = 392; two grid-stride iterations.
    // Alignment: OUT_W=1018 (even), plane even, gx even -> every float2
    // element offset is even -> 8B-aligned stores.
    const size_t plane = (size_t)OUT_H * OUT_W;
    float* ob = out + (size_t)b * NBINS * plane;
#pragma unroll
    for (int it = 0; it < 2; it++) {
        const int u = tid + it * NTHREADS;
        if (u < 14 * T) {
            const int r  = u / 14;
            const int c  = (u - r * 14) * 2;
            const int gy = oy + r, gx = ox + c;
            if (gy < OUT_H && gx + 1 < OUT_W) {
                const unsigned long long v0 = s_h[r][c]     + s_h[r + 1][c]
                                            + s_h[r + 2][c] + s_h[r + 3][c]
                                            + s_h[r + 4][c];
                const unsigned long long v1 = s_h[r][c + 1]     + s_h[r + 1][c + 1]
                                            + s_h[r + 2][c + 1] + s_h[r + 3][c + 1]
                                            + s_h[r + 4][c + 1];
                float* p = ob + (size_t)gy * OUT_W + gx;
#pragma unroll
                for (int bin = 0; bin < NBINS; bin++) {
                    float2 v;
                    v.x = (float)((unsigned)(v0 >> (5 * bin)) & 31u) * (1.0f / 25.0f);
                    v.y = (float)((unsigned)(v1 >> (5 * bin)) & 31u) * (1.0f / 25.0f);
                    *(float2*)(p + (size_t)bin * plane) = v;
                }
            }
        }
    }
}

extern "C" void kernel_launch(void* const* d_in, const int* in_sizes, int n_in,
                              void* d_out, int out_size)
{
    const float* x     = (const float*)d_in[0];   // [B,1,1024,1024]
    const float* masks = (const float*)d_in[1];   // [8,1,3,3]
    float* out = (float*)d_out;                   // [B,9,1018,1018]

    const int batch = in_sizes[0] / (1024 * 1024);

    dim3 grid((OUT_W + T - 1) / T, (OUT_H + T - 1) / T, batch);
    ehd_fused_kernel<<<grid, NTHREADS>>>(x, masks, out);
}

// round 5
// speedup vs baseline: 1.5964x; 1.1176x over previous
#include <cuda_runtime.h>

// EHD layer, fully fused, v4b (v4 with dp4a overload ambiguity fixed):
//   3x3 conv (8 filters) -> argmax+thresh -> one-hot -> 5x5 box mean.
//
// v4 vs v3:
//  - one-hot packed as BYTES of a u64 (bins 0..7; bin 8 implicit since the
//    9 window counts always sum to 25). Unpack = byte_perm + I2F + FMUL,
//    no 64-bit funnel shifts. bin8 = 25 - dp4a byte-sum.
//  - masks in __constant__ (async D2D copy at launch): removes 72 LDS per
//    thread and takes mask reads off the overloaded L1/shared pipe.

#define NOR    8
#define NBINS  9
#define OUT_H  1018
#define OUT_W  1018
#define THRESH 0.9f

#define T   28            // output tile
#define IT  32            // index tile  (T+4), power of 2
#define LT  34            // input tile  (T+6)

#define NTHREADS 256

__constant__ float c_masks[NOR * 9];

__global__ __launch_bounds__(NTHREADS, 5)
void ehd_fused_kernel(const float* __restrict__ x,
                      float* __restrict__ out)
{
    __shared__ float s_in[LT][36];                    // 34x36 f32
    __shared__ unsigned long long s_oh[IT][36];       // 32x36 byte-packed one-hot (cols 32..35 = 0)
    __shared__ unsigned long long s_h [IT][33];       // 32x33 horizontal 5-sums

    const int tid  = threadIdx.x;
    const int lane = tid & 31;
    const int wid  = tid >> 5;
    const int ox   = blockIdx.x * T;
    const int oy   = blockIdx.y * T;
    const int b    = blockIdx.z;

    if (tid < IT * 4) s_oh[tid >> 2][32 + (tid & 3)] = 0ULL;  // zero halo pad cols

    // ---- stage 1: load 34x34 input tile (zero-pad OOB; pad only feeds index
    // pixels no valid output window references) ----
    const float* xb = x + (size_t)b * (1024 * 1024);
    for (int r = wid; r < LT; r += 8) {
        const int gy = oy + r;
        for (int c = lane; c < LT; c += 32) {
            const int gx = ox + c;
            float v = 0.0f;
            if (gy < 1024 && gx < 1024) v = xb[gy * 1024 + gx];
            s_in[r][c] = v;
        }
    }
    __syncthreads();

    // ---- stage 2: conv + argmax + threshold + byte-packed one-hot ----
    // thread -> column c = lane, rows rbase..rbase+3 (shared 6x3 window strip)
    {
        const int c     = lane;
        const int rbase = wid << 2;

        float w[6][3];
#pragma unroll
        for (int j = 0; j < 6; j++)
#pragma unroll
            for (int k = 0; k < 3; k++)
                w[j][k] = s_in[rbase + j][c + k];

        float best[4];
        int   bi[4];
#pragma unroll
        for (int p = 0; p < 4; p++) { best[p] = -3.4e38f; bi[p] = 0; }

#pragma unroll
        for (int f = 0; f < NOR; f++) {
            const float m0 = c_masks[f * 9 + 0], m1 = c_masks[f * 9 + 1], m2 = c_masks[f * 9 + 2];
            const float m3 = c_masks[f * 9 + 3], m4 = c_masks[f * 9 + 4], m5 = c_masks[f * 9 + 5];
            const float m6 = c_masks[f * 9 + 6], m7 = c_masks[f * 9 + 7], m8 = c_masks[f * 9 + 8];
#pragma unroll
            for (int p = 0; p < 4; p++) {
                float acc = w[p][0] * m0;
                acc = fmaf(w[p    ][1], m1, acc);
                acc = fmaf(w[p    ][2], m2, acc);
                acc = fmaf(w[p + 1][0], m3, acc);
                acc = fmaf(w[p + 1][1], m4, acc);
                acc = fmaf(w[p + 1][2], m5, acc);
                acc = fmaf(w[p + 2][0], m6, acc);
                acc = fmaf(w[p + 2][1], m7, acc);
                acc = fmaf(w[p + 2][2], m8, acc);
                // strict > keeps FIRST max (jnp.argmax tie-break)
                if (acc > best[p]) { best[p] = acc; bi[p] = f; }
            }
        }
#pragma unroll
        for (int p = 0; p < 4; p++) {
            const int idx = (best[p] < THRESH) ? NOR : bi[p];
            // bins 0..7 -> one byte of a u64; bin 8 (no-edge) -> 0 (implicit)
            const unsigned long long oh =
                (idx < NOR) ? (1ULL << (idx << 3)) : 0ULL;
            s_oh[rbase + p][c] = oh;
        }
    }
    __syncthreads();

    // ---- stage 3: horizontal 5-tap sum on byte-packed words (max/byte = 5) ----
#pragma unroll
    for (int it = 0; it < 4; it++) {
        const int i = tid + it * NTHREADS;
        const int r = i >> 5, c = i & 31;
        s_h[r][c] = s_oh[r][c] + s_oh[r][c + 1] + s_oh[r][c + 2]
                  + s_oh[r][c + 3] + s_oh[r][c + 4];
    }
    __syncthreads();

    // ---- stage 4: vertical 5-tap sum on COLUMN PAIRS, unpack bytes, store ----
    // max per byte = 25 (< 256, no carry). 14 col-pairs x 28 rows = 392 units.
    const size_t plane = (size_t)OUT_H * OUT_W;
    float* ob = out + (size_t)b * NBINS * plane;
#pragma unroll
    for (int it = 0; it < 2; it++) {
        const int u = tid + it * NTHREADS;
        if (u < 14 * T) {
            const int r  = u / 14;
            const int c  = (u - r * 14) * 2;
            const int gy = oy + r, gx = ox + c;
            if (gy < OUT_H && gx + 1 < OUT_W) {
                const unsigned long long v0 = s_h[r][c]     + s_h[r + 1][c]
                                            + s_h[r + 2][c] + s_h[r + 3][c]
                                            + s_h[r + 4][c];
                const unsigned long long v1 = s_h[r][c + 1]     + s_h[r + 1][c + 1]
                                            + s_h[r + 2][c + 1] + s_h[r + 3][c + 1]
                                            + s_h[r + 4][c + 1];
                const unsigned lo0 = (unsigned)v0, hi0 = (unsigned)(v0 >> 32);
                const unsigned lo1 = (unsigned)v1, hi1 = (unsigned)(v1 >> 32);

                float* p = ob + (size_t)gy * OUT_W + gx;
#pragma unroll
                for (int bin = 0; bin < 8; bin++) {
                    const unsigned w0 = (bin < 4) ? lo0 : hi0;
                    const unsigned w1 = (bin < 4) ? lo1 : hi1;
                    const int sel = 0x4440 | (bin & 3);   // {0,0,0,byte[bin&3]}
                    float2 v;
                    v.x = (float)__byte_perm(w0, 0, sel) * (1.0f / 25.0f);
                    v.y = (float)__byte_perm(w1, 0, sel) * (1.0f / 25.0f);
                    *(float2*)(p + (size_t)bin * plane) = v;
                }
                // bin 8 = 25 - sum of the other 8 counts (dp4a byte-sum,
                // all-unsigned operands to avoid overload ambiguity)
                const unsigned s0 = __dp4a(lo0, 0x01010101u, __dp4a(hi0, 0x01010101u, 0u));
                const unsigned s1 = __dp4a(lo1, 0x01010101u, __dp4a(hi1, 0x01010101u, 0u));
                float2 v8;
                v8.x = (float)(25 - (int)s0) * (1.0f / 25.0f);
                v8.y = (float)(25 - (int)s1) * (1.0f / 25.0f);
                *(float2*)(p + (size_t)8 * plane) = v8;
            }
        }
    }
}

extern "C" void kernel_launch(void* const* d_in, const int* in_sizes, int n_in,
                              void* d_out, int out_size)
{
    const float* x     = (const float*)d_in[0];   // [B,1,1024,1024]
    const float* masks = (const float*)d_in[1];   // [8,1,3,3]
    float* out = (float*)d_out;                   // [B,9,1018,1018]

    const int batch = in_sizes[0] / (1024 * 1024);

    // masks -> constant bank (device-to-device async copy: graph-capturable)
    cudaMemcpyToSymbolAsync(c_masks, masks, NOR * 9 * sizeof(float), 0,
                            cudaMemcpyDeviceToDevice);

    dim3 grid((OUT_W + T - 1) / T, (OUT_H + T - 1) / T, batch);
    ehd_fused_kernel<<<grid, NTHREADS>>>(x, out);
}